// round 1
// baseline (speedup 1.0000x reference)
#include <cuda_runtime.h>
#include <cstdint>

// Problem constants
#define MAX_DIST 35.0f
#define BOX 71            // ceil(2*35/1 + 1)
#define FDIM 32
#define BATCH 8
#define NPTS 16384

// ---------------------------------------------------------------------------
// Kernel 1: zero the full output grid with float4 stores (grid-stride).
// out_size = 8*71*71*71*32 = 91,625,216 floats -> 22,906,304 float4.
// ---------------------------------------------------------------------------
__global__ void zero_grid_kernel(float4* __restrict__ out, long long n4) {
    long long i = (long long)blockIdx.x * blockDim.x + threadIdx.x;
    long long stride = (long long)gridDim.x * blockDim.x;
    const float4 z = make_float4(0.f, 0.f, 0.f, 0.f);
    for (; i < n4; i += stride) {
        out[i] = z;
    }
}

// ---------------------------------------------------------------------------
// Kernel 2: scatter-add. Each thread handles one (point, 4-feature quad):
//   tid -> point p = tid/8, quad q = tid%8 (8 quads of float4 cover F=32).
// All points (across all batches) scatter into batch slice 0, matching the
// reference's tf.zeros batch-index column.
// Out-of-box points add exactly 0.0 in the reference -> skip them.
// Rounding must be round-half-to-even (jnp.round) -> __float2int_rn.
// Uses red.global.add.v4.f32 (no-return vector reduction, sm_90+).
// ---------------------------------------------------------------------------
__global__ void scatter_kernel(const float* __restrict__ coords,
                               const float4* __restrict__ features4,
                               float* __restrict__ out) {
    int tid = blockIdx.x * blockDim.x + threadIdx.x;
    const int total = BATCH * NPTS * (FDIM / 4);   // 1,048,576 threads
    if (tid >= total) return;

    int p = tid >> 3;        // global point index (b*N + n)
    int q = tid & 7;         // which float4 of the 8 covering F=32

    // coords[p*3 .. p*3+2] — 8 threads per point read same addrs (L1 broadcast)
    float c0 = __ldg(&coords[p * 3 + 0]);
    float c1 = __ldg(&coords[p * 3 + 1]);
    float c2 = __ldg(&coords[p * 3 + 2]);

    int g0 = __float2int_rn(c0 + MAX_DIST);
    int g1 = __float2int_rn(c1 + MAX_DIST);
    int g2 = __float2int_rn(c2 + MAX_DIST);

    // unsigned compare does both >=0 and <BOX checks
    if ((unsigned)g0 >= BOX || (unsigned)g1 >= BOX || (unsigned)g2 >= BOX)
        return;

    float4 v = __ldg(&features4[(long long)p * 8 + q]);

    long long cell = ((long long)g0 * BOX + g1) * BOX + g2;
    float* dst = out + cell * FDIM + q * 4;   // batch slice 0

    asm volatile("red.global.add.v4.f32 [%0], {%1, %2, %3, %4};"
                 :: "l"(dst), "f"(v.x), "f"(v.y), "f"(v.z), "f"(v.w)
                 : "memory");
}

extern "C" void kernel_launch(void* const* d_in, const int* in_sizes, int n_in,
                              void* d_out, int out_size) {
    const float* coords = (const float*)d_in[0];     // [8,16384,3] f32
    const float4* feats = (const float4*)d_in[1];    // [8,16384,32] f32 as float4
    float* out = (float*)d_out;                      // [8,71,71,71,32] f32

    long long n4 = (long long)out_size / 4;          // float4 count
    int zthreads = 256;
    int zblocks = 148 * 16;                          // grid-stride, full chip
    zero_grid_kernel<<<zblocks, zthreads>>>((float4*)out, n4);

    const int total = BATCH * NPTS * (FDIM / 4);
    int sthreads = 256;
    int sblocks = (total + sthreads - 1) / sthreads;
    scatter_kernel<<<sblocks, sthreads>>>(coords, feats, out);
}

// round 2
// speedup vs baseline: 1.0234x; 1.0234x over previous
#include <cuda_runtime.h>
#include <cstdint>

// Problem constants
#define MAX_DIST 35.0f
#define BOX 71            // ceil(2*35/1 + 1)
#define FDIM 32
#define BATCH 8
#define NPTS 16384

// Derived sizes (in float4 units)
#define SLICE0_F4 (BOX * BOX * BOX * FDIM / 4)          // 2,863,288
#define TOTAL_F4  (BATCH * BOX * BOX * BOX * FDIM / 4)  // 22,906,304
#define SCATTER_THREADS (BATCH * NPTS * (FDIM / 4))     // 1,048,576

// ---------------------------------------------------------------------------
// Kernel A: zero ONLY batch slice 0 (45.8 MB) — the only region the scatter
// atomics depend on. One wave, pure streaming stores.
// ---------------------------------------------------------------------------
__global__ void zero_slice0_kernel(float4* __restrict__ out) {
    int i = blockIdx.x * blockDim.x + threadIdx.x;
    int stride = gridDim.x * blockDim.x;
    const float4 z = make_float4(0.f, 0.f, 0.f, 0.f);
    for (; i < SLICE0_F4; i += stride) {
        __stcs(&out[i], z);
    }
}

// ---------------------------------------------------------------------------
// Kernel B (fused): each thread
//   (1) performs its scatter-add into slice 0 (latency-bound; hidden under
//       the streaming stores of sibling warps), then
//   (2) grid-strides over slices 1..7 (320 MB) writing zeros.
// Fusing within-thread (not by block role) keeps both kinds of work
// co-resident on every SM for true overlap.
//
// Scatter semantics (faithful to reference):
//   - all B*N points land in batch slice 0 (reference's tf.zeros batch col)
//   - round-half-to-even via __float2int_rn (jnp.round)
//   - out-of-box points contribute exactly +0.0 -> skipped
//   - red.global.add.v4.f32: no-return vector reduction (REDG path)
// ---------------------------------------------------------------------------
__global__ void fused_scatter_zero_kernel(const float* __restrict__ coords,
                                          const float4* __restrict__ features4,
                                          float* __restrict__ out) {
    const int tid = blockIdx.x * blockDim.x + threadIdx.x;

    // ---- Phase 1: scatter (tid < SCATTER_THREADS always true for our grid) ----
    {
        int p = tid >> 3;        // global point index (b*N + n)
        int q = tid & 7;         // which float4 of the 8 covering F=32

        float c0 = __ldg(&coords[p * 3 + 0]);
        float c1 = __ldg(&coords[p * 3 + 1]);
        float c2 = __ldg(&coords[p * 3 + 2]);

        int g0 = __float2int_rn(c0 + MAX_DIST);
        int g1 = __float2int_rn(c1 + MAX_DIST);
        int g2 = __float2int_rn(c2 + MAX_DIST);

        if ((unsigned)g0 < BOX && (unsigned)g1 < BOX && (unsigned)g2 < BOX) {
            float4 v = __ldg(&features4[(long long)p * 8 + q]);
            int cell = (g0 * BOX + g1) * BOX + g2;
            float* dst = out + (long long)cell * FDIM + q * 4;  // batch slice 0
            asm volatile("red.global.add.v4.f32 [%0], {%1, %2, %3, %4};"
                         :: "l"(dst), "f"(v.x), "f"(v.y), "f"(v.z), "f"(v.w)
                         : "memory");
        }
    }

    // ---- Phase 2: zero slices 1..7 (grid-stride, streaming stores) ----
    float4* out4 = (float4*)out;
    const float4 z = make_float4(0.f, 0.f, 0.f, 0.f);
    for (long long i = SLICE0_F4 + tid; i < TOTAL_F4; i += SCATTER_THREADS) {
        __stcs(&out4[i], z);
    }
}

extern "C" void kernel_launch(void* const* d_in, const int* in_sizes, int n_in,
                              void* d_out, int out_size) {
    const float* coords = (const float*)d_in[0];     // [8,16384,3] f32
    const float4* feats = (const float4*)d_in[1];    // [8,16384,32] f32 as float4
    float* out = (float*)d_out;                      // [8,71,71,71,32] f32

    // Kernel A: zero slice 0 — one full wave of the chip
    zero_slice0_kernel<<<148 * 8, 256>>>((float4*)out);

    // Kernel B: fused scatter + zero of slices 1..7
    const int blocks = SCATTER_THREADS / 256;        // 4096
    fused_scatter_zero_kernel<<<blocks, 256>>>(coords, feats, out);
}